// round 2
// baseline (speedup 1.0000x reference)
#include <cuda_runtime.h>
#include <math.h>

#define Nn    20000
#define HIDF  256
#define ZF    64
#define EP    120000
#define E2    240000
#define ENEG  600000
#define ETOT  720000

typedef unsigned long long ull;

// ---------------- scratch (static device globals; no allocation) ----------------
__device__ float g_m[Nn * HIDF];        // x@W1
__device__ float g_agg[Nn * HIDF];      // scatter target layer1
__device__ float g_h1[Nn * HIDF];       // post LN+relu
__device__ float g_tmulv[Nn * 128];     // [h1@Wmu | h1@Wlv]
__device__ float g_mulv[Nn * 128];      // scattered
__device__ float g_z[Nn * ZF];
__device__ float g_md[Nn * ZF];         // decoder gemm out (reused both passes)
__device__ float g_hd[Nn * ZF];         // decoder layer1 agg / h
__device__ float g_hd2[Nn * ZF];        // decoder layer2 agg / h
__device__ float g_A12[Nn * 128];       // [h@Wa1 | h@Wa2]
__device__ float g_dis[Nn];
__device__ int   g_deg[Nn];
__device__ double g_acc[2];             // [recon_sum, kl_sum]

#define FMA2(c, a, b) asm("fma.rn.f32x2 %0, %1, %2, %0;" : "+l"(c) : "l"(a), "l"(b))

// ---------------- generic SGEMM: C[M,ldc](+coff) = A[M,K] @ B[K,Ncols] ----------------
// BM=64, BN=64, BK=16, 256 threads, 4x4 microtile with f32x2 accumulation.
__global__ __launch_bounds__(256) void sgemm_kernel(
    const float* __restrict__ A, const float* __restrict__ B, float* __restrict__ C,
    int M, int Ncols, int K, int ldc, int coff)
{
    __shared__ float As2[16][128];   // A value duplicated in pairs -> LDS.64 gives {a,a}
    __shared__ float Bs[16][64];
    int tid = threadIdx.x;
    int m0 = blockIdx.y * 64;
    int n0 = blockIdx.x * 64;
    int ty = tid >> 4, tx = tid & 15;
    int am = tid >> 2, ak = (tid & 3) * 4;
    int bk = tid >> 4, bn = (tid & 15) * 4;

    ull acc[4][2];
#pragma unroll
    for (int i = 0; i < 4; i++) { acc[i][0] = 0ull; acc[i][1] = 0ull; }

    for (int k0 = 0; k0 < K; k0 += 16) {
        float4 va = make_float4(0.f, 0.f, 0.f, 0.f);
        int gm = m0 + am;
        if (gm < M) va = *(const float4*)(A + (size_t)gm * K + k0 + ak);
        As2[ak + 0][2 * am] = va.x; As2[ak + 0][2 * am + 1] = va.x;
        As2[ak + 1][2 * am] = va.y; As2[ak + 1][2 * am + 1] = va.y;
        As2[ak + 2][2 * am] = va.z; As2[ak + 2][2 * am + 1] = va.z;
        As2[ak + 3][2 * am] = va.w; As2[ak + 3][2 * am + 1] = va.w;
        *(float4*)&Bs[bk][bn] = *(const float4*)(B + (size_t)(k0 + bk) * Ncols + n0 + bn);
        __syncthreads();
#pragma unroll
        for (int kk = 0; kk < 16; kk++) {
            ull a0 = *(const ull*)&As2[kk][(ty * 4 + 0) * 2];
            ull a1 = *(const ull*)&As2[kk][(ty * 4 + 1) * 2];
            ull a2 = *(const ull*)&As2[kk][(ty * 4 + 2) * 2];
            ull a3 = *(const ull*)&As2[kk][(ty * 4 + 3) * 2];
            union { float4 f4; ull u[2]; } bu;
            bu.f4 = *(const float4*)&Bs[kk][tx * 4];
            FMA2(acc[0][0], a0, bu.u[0]); FMA2(acc[0][1], a0, bu.u[1]);
            FMA2(acc[1][0], a1, bu.u[0]); FMA2(acc[1][1], a1, bu.u[1]);
            FMA2(acc[2][0], a2, bu.u[0]); FMA2(acc[2][1], a2, bu.u[1]);
            FMA2(acc[3][0], a3, bu.u[0]); FMA2(acc[3][1], a3, bu.u[1]);
        }
        __syncthreads();
    }
#pragma unroll
    for (int i = 0; i < 4; i++) {
        int gm = m0 + ty * 4 + i;
        if (gm < M) {
            union { ull u[2]; float f[4]; } r;
            r.u[0] = acc[i][0]; r.u[1] = acc[i][1];
            *(float4*)(C + (size_t)gm * ldc + coff + n0 + tx * 4) =
                make_float4(r.f[0], r.f[1], r.f[2], r.f[3]);
        }
    }
}

// ---------------- scatter add: out[dst[e]*F + f] += m[src[e]*F + f] ----------------
__global__ void scatter_add_kernel(const float* __restrict__ m, const int* __restrict__ src,
                                   const int* __restrict__ dst, float* __restrict__ out,
                                   int nE, int lgF)
{
    int idx = blockIdx.x * blockDim.x + threadIdx.x;
    int total = nE << lgF;
    if (idx >= total) return;
    int e = idx >> lgF;
    int f = idx & ((1 << lgF) - 1);
    atomicAdd(&out[((size_t)dst[e] << lgF) + f], m[((size_t)src[e] << lgF) + f]);
}

// ---------------- LayerNorm + bias + relu (row of 256) ----------------
__global__ __launch_bounds__(256) void ln_relu_kernel(
    const float* __restrict__ agg, const float* __restrict__ b1,
    const float* __restrict__ g1, const float* __restrict__ bt1, float* __restrict__ h1)
{
    int row = blockIdx.x;
    int tid = threadIdx.x;
    int lane = tid & 31, w = tid >> 5;
    float v = agg[(size_t)row * 256 + tid] + b1[tid];
    __shared__ float red[8];
    float s = v;
#pragma unroll
    for (int o = 16; o; o >>= 1) s += __shfl_xor_sync(0xffffffffu, s, o);
    if (lane == 0) red[w] = s;
    __syncthreads();
    float tot = 0.f;
#pragma unroll
    for (int i = 0; i < 8; i++) tot += red[i];
    float mu = tot * (1.f / 256.f);
    __syncthreads();
    float d = v - mu;
    float q = d * d;
#pragma unroll
    for (int o = 16; o; o >>= 1) q += __shfl_xor_sync(0xffffffffu, q, o);
    if (lane == 0) red[w] = q;
    __syncthreads();
    float tq = 0.f;
#pragma unroll
    for (int i = 0; i < 8; i++) tq += red[i];
    float var = tq * (1.f / 256.f);
    float o = d * rsqrtf(var + 1e-5f) * g1[tid] + bt1[tid];
    h1[(size_t)row * 256 + tid] = fmaxf(o, 0.f);
}

__device__ __forceinline__ void block_reduce_add_double(double v, double* gout)
{
    int lane = threadIdx.x & 31, w = threadIdx.x >> 5;
#pragma unroll
    for (int o = 16; o; o >>= 1) v += __shfl_xor_sync(0xffffffffu, v, o);
    __shared__ double s[8];
    if (lane == 0) s[w] = v;
    __syncthreads();
    if (threadIdx.x == 0) {
        double t = 0.0;
        int nw = (blockDim.x + 31) >> 5;
        for (int i = 0; i < nw; i++) t += s[i];
        atomicAdd(gout, t);
    }
}

// ---------------- z = mu + eps*exp(0.5*lv);  kl term accumulation ----------------
__global__ __launch_bounds__(256) void z_kl_kernel(
    const float* __restrict__ mulv, const float* __restrict__ eps,
    const float* __restrict__ bmu, const float* __restrict__ blv,
    float* __restrict__ z, double* __restrict__ acc)
{
    int idx = blockIdx.x * blockDim.x + threadIdx.x;
    float local = 0.f;
    if (idx < Nn * ZF) {
        int n = idx >> 6, j = idx & 63;
        float mu = mulv[(size_t)n * 128 + j] + bmu[j];
        float lv = mulv[(size_t)n * 128 + 64 + j] + blv[j];
        z[idx] = mu + eps[idx] * expf(0.5f * lv);
        local = 1.f + lv - mu * mu - expf(lv);
    }
    block_reduce_add_double((double)local, acc + 1);
}

__global__ void deg_kernel(const int* __restrict__ pd, int* __restrict__ deg)
{
    int e = blockIdx.x * blockDim.x + threadIdx.x;
    if (e < EP) atomicAdd(&deg[pd[e]], 1);
}

__global__ void dis_kernel(const int* __restrict__ deg, float* __restrict__ dis)
{
    int n = blockIdx.x * blockDim.x + threadIdx.x;
    if (n < Nn) dis[n] = rsqrtf((float)(deg[n] + 1));
}

// ---------------- normalized scatter for decoder GCN ----------------
__global__ void scatter_norm_kernel(const float* __restrict__ m, const int* __restrict__ ps,
                                    const int* __restrict__ pd, const float* __restrict__ dis,
                                    float* __restrict__ out)
{
    int idx = blockIdx.x * blockDim.x + threadIdx.x;
    if (idx >= EP * 64) return;
    int e = idx >> 6, f = idx & 63;
    int s = ps[e], d = pd[e];
    atomicAdd(&out[((size_t)d << 6) + f], m[((size_t)s << 6) + f] * dis[s] * dis[d]);
}

// ---------------- decoder finalize: self-loop + bias + relu (in place OK) ----------------
__global__ void dec_fin_kernel(const float* aggv, const float* __restrict__ m,
                               const float* __restrict__ dis, const float* __restrict__ bd,
                               float* outp)
{
    int idx = blockIdx.x * blockDim.x + threadIdx.x;
    if (idx >= Nn * 64) return;
    int n = idx >> 6, j = idx & 63;
    float di = dis[n];
    float v = aggv[idx] + m[idx] * di * di + bd[j];
    outp[idx] = fmaxf(v, 0.f);
}

// ---------------- fused edge decoder + BCE loss ----------------
// t[e,:] = A1[u] + A2[v] + |hu-hv|@Wa3 + (hu*hv)@Wa4 + ba ; relu ; @Wb + bb ; /tau ; BCE
// 32 edges/tile, 256 threads; thread(j = tid&63, erow = tid>>6) owns 8 edges (4 f32x2 accs).
__global__ __launch_bounds__(256) void edge_loss_kernel(
    const float* __restrict__ h, const float* __restrict__ A12,
    const float* __restrict__ Wa, const float* __restrict__ ba,
    const float* __restrict__ Wb, const float* __restrict__ bb,
    const float* __restrict__ tau,
    const int* __restrict__ pu, const int* __restrict__ pv,
    const int* __restrict__ nu, const int* __restrict__ nv,
    double* __restrict__ acc)
{
    extern __shared__ float sm[];
    float* sW = sm;                 // [128][64]   = 8192
    float* sF = sW + 8192;          // [128][32]   = 4096 (k-major, edge-fast)
    float* sHU = sF + 4096;         // [32][65]    = 2080 (padded vs bank conflicts)
    float* sHV = sHU + 2080;        // 2080
    float* sLogit = sHV + 2080;     // 32
    int* sU = (int*)(sLogit + 32);  // 32
    int* sV = sU + 32;              // 32

    int tid = threadIdx.x;
    int lane = tid & 31, wid = tid >> 5;
    int j = tid & 63, erow = tid >> 6;

    const float* W34 = Wa + 128 * 64;
    for (int i = tid; i < 8192; i += 256) sW[i] = W34[i];

    float tc = fmaxf(tau[0], 1e-4f);
    float invt = 1.0f / tc;
    float bbv = bb[0];
    float baj = ba[j];
    float wbj = Wb[j];
    const float pw = (float)ENEG / (float)EP;
    double dsum = 0.0;

    int nTiles = ETOT / 32;  // 22500, exact
    for (int tile = blockIdx.x; tile < nTiles; tile += gridDim.x) {
        __syncthreads();  // previous tile fully consumed (also orders sW load on iter 0)
        if (tid < 32) {
            int ge = tile * 32 + tid;
            int u, v;
            if (ge < EP) { u = pu[ge]; v = pv[ge]; }
            else         { u = nu[ge - EP]; v = nv[ge - EP]; }
            sU[tid] = u; sV[tid] = v;
            sLogit[tid] = 0.f;
        }
        __syncthreads();
        // phase A: coalesced gather of h rows (warp per 4 edges)
#pragma unroll
        for (int ee = 0; ee < 4; ee++) {
            int e = wid * 4 + ee;
            int u = sU[e], v = sV[e];
            sHU[e * 65 + lane]      = h[(size_t)u * 64 + lane];
            sHU[e * 65 + 32 + lane] = h[(size_t)u * 64 + 32 + lane];
            sHV[e * 65 + lane]      = h[(size_t)v * 64 + lane];
            sHV[e * 65 + 32 + lane] = h[(size_t)v * 64 + 32 + lane];
        }
        __syncthreads();
        // phase B: transpose + feature build (conflict-free both sides)
#pragma unroll
        for (int p = 0; p < 8; p++) {
            int i = tid + p * 256;
            int e = i & 31, f = i >> 5;
            float hu = sHU[e * 65 + f], hv = sHV[e * 65 + f];
            sF[f * 32 + e]        = fabsf(hu - hv);
            sF[(64 + f) * 32 + e] = hu * hv;
        }
        __syncthreads();
        // mainloop: 128 k-steps, FFMA2-floor bound
        ull a0 = 0, a1 = 0, a2 = 0, a3 = 0;
        const float* fbase = sF + erow * 8;
#pragma unroll 4
        for (int k = 0; k < 128; k++) {
            float w = sW[k * 64 + j];
            ull w2;
            asm("mov.b64 %0, {%1, %1};" : "=l"(w2) : "f"(w));
            ulonglong2 fA = *(const ulonglong2*)(fbase + k * 32);
            ulonglong2 fB = *(const ulonglong2*)(fbase + k * 32 + 4);
            FMA2(a0, fA.x, w2); FMA2(a1, fA.y, w2);
            FMA2(a2, fB.x, w2); FMA2(a3, fB.y, w2);
        }
        // epilogue: + A1[u] + A2[v] + ba, relu, *Wb, reduce over j
        union { ull u; float f[2]; } c0, c1, c2, c3;
        c0.u = a0; c1.u = a1; c2.u = a2; c3.u = a3;
        float vals[8] = {c0.f[0], c0.f[1], c1.f[0], c1.f[1],
                         c2.f[0], c2.f[1], c3.f[0], c3.f[1]};
#pragma unroll
        for (int q = 0; q < 8; q++) {
            int e = erow * 8 + q;
            int u = sU[e], v = sV[e];
            float t = vals[q] + A12[(size_t)u * 128 + j] + A12[(size_t)v * 128 + 64 + j] + baj;
            float r = fmaxf(t, 0.f) * wbj;
#pragma unroll
            for (int o = 16; o; o >>= 1) r += __shfl_xor_sync(0xffffffffu, r, o);
            if (lane == 0) atomicAdd(&sLogit[e], r);
        }
        __syncthreads();
        if (tid < 32) {
            float l = (sLogit[tid] + bbv) * invt;
            int ge = tile * 32 + tid;
            float term;
            if (ge < EP) {
                float ls = fminf(l, 0.f) - log1pf(expf(-fabsf(l)));   // log_sigmoid(l)
                term = pw * ls;
            } else {
                float ls = fminf(-l, 0.f) - log1pf(expf(-fabsf(l)));  // log_sigmoid(-l)
                term = ls;
            }
            dsum += (double)term;
        }
    }
    __syncthreads();
#pragma unroll
    for (int o = 16; o; o >>= 1) dsum += __shfl_xor_sync(0xffffffffu, dsum, o);
    __shared__ double sred[8];
    if (lane == 0) sred[wid] = dsum;
    __syncthreads();
    if (tid == 0) {
        double t = 0.0;
        for (int i = 0; i < 8; i++) t += sred[i];
        atomicAdd(acc, t);
    }
}

__global__ void finalize_kernel(const double* __restrict__ acc, float* __restrict__ out, int n)
{
    double recon = -acc[0] / (double)ETOT;
    double kl = -0.5 * acc[1] / ((double)Nn * 64.0);
    if (n >= 3) {
        out[0] = (float)(recon + kl);
        out[1] = (float)recon;
        out[2] = (float)kl;
    } else {
        out[0] = (float)(recon + kl);
    }
}

// ---------------- launch ----------------
extern "C" void kernel_launch(void* const* d_in, const int* in_sizes, int n_in,
                              void* d_out, int out_size)
{
    const float* x   = (const float*)d_in[0];
    const float* eps = (const float*)d_in[1];
    const int* edge_index = (const int*)d_in[2];
    const int* pos_edge   = (const int*)d_in[3];
    const int* neg_edge   = (const int*)d_in[4];
    const float* W1  = (const float*)d_in[5];
    const float* b1  = (const float*)d_in[6];
    const float* g1  = (const float*)d_in[7];
    const float* bt1 = (const float*)d_in[8];
    const float* Wmu = (const float*)d_in[9];
    const float* bmu = (const float*)d_in[10];
    const float* Wlv = (const float*)d_in[11];
    const float* blv = (const float*)d_in[12];
    const float* Wd1 = (const float*)d_in[13];
    const float* bd1 = (const float*)d_in[14];
    const float* Wd2 = (const float*)d_in[15];
    const float* bd2 = (const float*)d_in[16];
    const float* Wa  = (const float*)d_in[17];
    const float* ba  = (const float*)d_in[18];
    const float* Wb  = (const float*)d_in[19];
    const float* bb  = (const float*)d_in[20];
    const float* tau = (const float*)d_in[21];

    float *p_m, *p_agg, *p_h1, *p_tmulv, *p_mulv, *p_z, *p_md, *p_hd, *p_hd2, *p_A12, *p_dis;
    int* p_deg;
    double* p_acc;
    cudaGetSymbolAddress((void**)&p_m, g_m);
    cudaGetSymbolAddress((void**)&p_agg, g_agg);
    cudaGetSymbolAddress((void**)&p_h1, g_h1);
    cudaGetSymbolAddress((void**)&p_tmulv, g_tmulv);
    cudaGetSymbolAddress((void**)&p_mulv, g_mulv);
    cudaGetSymbolAddress((void**)&p_z, g_z);
    cudaGetSymbolAddress((void**)&p_md, g_md);
    cudaGetSymbolAddress((void**)&p_hd, g_hd);
    cudaGetSymbolAddress((void**)&p_hd2, g_hd2);
    cudaGetSymbolAddress((void**)&p_A12, g_A12);
    cudaGetSymbolAddress((void**)&p_dis, g_dis);
    cudaGetSymbolAddress((void**)&p_deg, g_deg);
    cudaGetSymbolAddress((void**)&p_acc, g_acc);

    const int* src = edge_index;
    const int* dst = edge_index + E2;
    const int* pu = pos_edge;
    const int* pv = pos_edge + EP;
    const int* nu = neg_edge;
    const int* nv = neg_edge + ENEG;

    // ---- encoder layer 1 ----
    cudaMemsetAsync(p_agg, 0, sizeof(float) * (size_t)Nn * HIDF);
    {
        dim3 g(4, (Nn + 63) / 64);
        sgemm_kernel<<<g, 256>>>(x, W1, p_m, Nn, 256, 256, 256, 0);
    }
    {
        int total = E2 * 256;
        scatter_add_kernel<<<(total + 255) / 256, 256>>>(p_m, src, dst, p_agg, E2, 8);
    }
    ln_relu_kernel<<<Nn, 256>>>(p_agg, b1, g1, bt1, p_h1);

    // ---- mu / logvar ----
    {
        dim3 g(1, (Nn + 63) / 64);
        sgemm_kernel<<<g, 256>>>(p_h1, Wmu, p_tmulv, Nn, 64, 256, 128, 0);
        sgemm_kernel<<<g, 256>>>(p_h1, Wlv, p_tmulv, Nn, 64, 256, 128, 64);
    }
    cudaMemsetAsync(p_mulv, 0, sizeof(float) * (size_t)Nn * 128);
    {
        int total = E2 * 128;
        scatter_add_kernel<<<(total + 255) / 256, 256>>>(p_tmulv, src, dst, p_mulv, E2, 7);
    }
    cudaMemsetAsync(p_acc, 0, 2 * sizeof(double));
    z_kl_kernel<<<(Nn * 64 + 255) / 256, 256>>>(p_mulv, eps, bmu, blv, p_z, p_acc);

    // ---- decoder normalization ----
    cudaMemsetAsync(p_deg, 0, sizeof(int) * Nn);
    deg_kernel<<<(EP + 255) / 256, 256>>>(pv, p_deg);
    dis_kernel<<<(Nn + 255) / 256, 256>>>(p_deg, p_dis);

    // ---- decoder GCN pass 1 ----
    {
        dim3 g(1, (Nn + 63) / 64);
        sgemm_kernel<<<g, 256>>>(p_z, Wd1, p_md, Nn, 64, 64, 64, 0);
    }
    cudaMemsetAsync(p_hd, 0, sizeof(float) * (size_t)Nn * 64);
    scatter_norm_kernel<<<(EP * 64 + 255) / 256, 256>>>(p_md, pu, pv, p_dis, p_hd);
    dec_fin_kernel<<<(Nn * 64 + 255) / 256, 256>>>(p_hd, p_md, p_dis, bd1, p_hd);

    // ---- decoder GCN pass 2 ----
    {
        dim3 g(1, (Nn + 63) / 64);
        sgemm_kernel<<<g, 256>>>(p_hd, Wd2, p_md, Nn, 64, 64, 64, 0);
    }
    cudaMemsetAsync(p_hd2, 0, sizeof(float) * (size_t)Nn * 64);
    scatter_norm_kernel<<<(EP * 64 + 255) / 256, 256>>>(p_md, pu, pv, p_dis, p_hd2);
    dec_fin_kernel<<<(Nn * 64 + 255) / 256, 256>>>(p_hd2, p_md, p_dis, bd2, p_hd2);

    // ---- per-node precompute of hu@Wa1, hv@Wa2 ----
    {
        dim3 g(1, (Nn + 63) / 64);
        sgemm_kernel<<<g, 256>>>(p_hd2, Wa, p_A12, Nn, 64, 64, 128, 0);
        sgemm_kernel<<<g, 256>>>(p_hd2, Wa + 64 * 64, p_A12, Nn, 64, 64, 128, 64);
    }

    // ---- fused edge decoder + loss ----
    {
        int smem = (8192 + 4096 + 2080 + 2080 + 32) * 4 + 64 * 4;
        cudaFuncSetAttribute(edge_loss_kernel, cudaFuncAttributeMaxDynamicSharedMemorySize, smem);
        edge_loss_kernel<<<444, 256, smem>>>(p_hd2, p_A12, Wa, ba, Wb, bb, tau,
                                             pu, pv, nu, nv, p_acc);
    }

    finalize_kernel<<<1, 1>>>(p_acc, (float*)d_out, out_size);

    (void)in_sizes; (void)n_in;
}

// round 4
// speedup vs baseline: 1.1953x; 1.1953x over previous
#include <cuda_runtime.h>
#include <math.h>

#define Nn    20000
#define HIDF  256
#define ZF    64
#define EP    120000
#define E2    240000
#define ENEG  600000
#define ETOT  720000

typedef unsigned long long ull;

// ---------------- scratch (static device globals; no allocation) ----------------
__device__ __align__(16) float g_m[Nn * HIDF];        // x@W1
__device__ __align__(16) float g_agg[Nn * HIDF];      // scatter target layer1
__device__ __align__(16) float g_h1[Nn * HIDF];       // post LN+relu
__device__ __align__(16) float g_tmulv[Nn * 128];     // [h1@Wmu | h1@Wlv]
__device__ __align__(16) float g_mulv[Nn * 128];      // scattered
__device__ __align__(16) float g_z[Nn * ZF];
__device__ __align__(16) float g_md[Nn * ZF];         // decoder gemm out (reused both passes)
__device__ __align__(16) float g_hd[Nn * ZF];         // decoder layer1 agg / h
__device__ __align__(16) float g_hd2[Nn * ZF];        // decoder layer2 agg / h
__device__ __align__(16) float g_A12[Nn * 128];       // [h@Wa1 | h@Wa2]
__device__ float g_dis[Nn];
__device__ int   g_deg[Nn];
__device__ double g_acc[2];             // [recon_sum, kl_sum]

#define FMA2(c, a, b) asm("fma.rn.f32x2 %0, %1, %2, %0;" : "+l"(c) : "l"(a), "l"(b))

__device__ __forceinline__ void red_add_v4(float* p, float4 v)
{
    asm volatile("red.global.add.v4.f32 [%0], {%1, %2, %3, %4};"
                 :: "l"(p), "f"(v.x), "f"(v.y), "f"(v.z), "f"(v.w) : "memory");
}

// ---------------- generic SGEMM: C[M,ldc](+coff) = A[M,K] @ B[K,Ncols] ----------------
__global__ __launch_bounds__(256) void sgemm_kernel(
    const float* __restrict__ A, const float* __restrict__ B, float* __restrict__ C,
    int M, int Ncols, int K, int ldc, int coff)
{
    __shared__ float As2[16][128];   // A value duplicated in pairs -> LDS.64 gives {a,a}
    __shared__ float Bs[16][64];
    int tid = threadIdx.x;
    int m0 = blockIdx.y * 64;
    int n0 = blockIdx.x * 64;
    int ty = tid >> 4, tx = tid & 15;
    int am = tid >> 2, ak = (tid & 3) * 4;
    int bk = tid >> 4, bn = (tid & 15) * 4;

    ull acc[4][2];
#pragma unroll
    for (int i = 0; i < 4; i++) { acc[i][0] = 0ull; acc[i][1] = 0ull; }

    for (int k0 = 0; k0 < K; k0 += 16) {
        float4 va = make_float4(0.f, 0.f, 0.f, 0.f);
        int gm = m0 + am;
        if (gm < M) va = *(const float4*)(A + (size_t)gm * K + k0 + ak);
        As2[ak + 0][2 * am] = va.x; As2[ak + 0][2 * am + 1] = va.x;
        As2[ak + 1][2 * am] = va.y; As2[ak + 1][2 * am + 1] = va.y;
        As2[ak + 2][2 * am] = va.z; As2[ak + 2][2 * am + 1] = va.z;
        As2[ak + 3][2 * am] = va.w; As2[ak + 3][2 * am + 1] = va.w;
        *(float4*)&Bs[bk][bn] = *(const float4*)(B + (size_t)(k0 + bk) * Ncols + n0 + bn);
        __syncthreads();
#pragma unroll
        for (int kk = 0; kk < 16; kk++) {
            ull a0 = *(const ull*)&As2[kk][(ty * 4 + 0) * 2];
            ull a1 = *(const ull*)&As2[kk][(ty * 4 + 1) * 2];
            ull a2 = *(const ull*)&As2[kk][(ty * 4 + 2) * 2];
            ull a3 = *(const ull*)&As2[kk][(ty * 4 + 3) * 2];
            union { float4 f4; ull u[2]; } bu;
            bu.f4 = *(const float4*)&Bs[kk][tx * 4];
            FMA2(acc[0][0], a0, bu.u[0]); FMA2(acc[0][1], a0, bu.u[1]);
            FMA2(acc[1][0], a1, bu.u[0]); FMA2(acc[1][1], a1, bu.u[1]);
            FMA2(acc[2][0], a2, bu.u[0]); FMA2(acc[2][1], a2, bu.u[1]);
            FMA2(acc[3][0], a3, bu.u[0]); FMA2(acc[3][1], a3, bu.u[1]);
        }
        __syncthreads();
    }
#pragma unroll
    for (int i = 0; i < 4; i++) {
        int gm = m0 + ty * 4 + i;
        if (gm < M) {
            union { ull u[2]; float f[4]; } r;
            r.u[0] = acc[i][0]; r.u[1] = acc[i][1];
            *(float4*)(C + (size_t)gm * ldc + coff + n0 + tx * 4) =
                make_float4(r.f[0], r.f[1], r.f[2], r.f[3]);
        }
    }
}

// ---------------- vectorized scatter add: out[dst[e]] += m[src[e]] (rows of 4*F4 floats) ----------------
// lgF4 = log2(row_floats/4). One thread = one float4 of one edge.
__global__ __launch_bounds__(256) void scatter_add_v4_kernel(
    const float4* __restrict__ m, const int* __restrict__ src,
    const int* __restrict__ dst, float* __restrict__ out, int nE, int lgF4)
{
    int idx = blockIdx.x * blockDim.x + threadIdx.x;
    int total = nE << lgF4;
    if (idx >= total) return;
    int e = idx >> lgF4;
    int f = idx & ((1 << lgF4) - 1);
    float4 v = m[((size_t)src[e] << lgF4) + f];
    red_add_v4(out + ((((size_t)dst[e] << lgF4) + f) << 2), v);
}

// ---------------- LayerNorm + bias + relu (row of 256) ----------------
__global__ __launch_bounds__(256) void ln_relu_kernel(
    const float* __restrict__ agg, const float* __restrict__ b1,
    const float* __restrict__ g1, const float* __restrict__ bt1, float* __restrict__ h1)
{
    int row = blockIdx.x;
    int tid = threadIdx.x;
    int lane = tid & 31, w = tid >> 5;
    float v = agg[(size_t)row * 256 + tid] + b1[tid];
    __shared__ float red[8];
    float s = v;
#pragma unroll
    for (int o = 16; o; o >>= 1) s += __shfl_xor_sync(0xffffffffu, s, o);
    if (lane == 0) red[w] = s;
    __syncthreads();
    float tot = 0.f;
#pragma unroll
    for (int i = 0; i < 8; i++) tot += red[i];
    float mu = tot * (1.f / 256.f);
    __syncthreads();
    float d = v - mu;
    float q = d * d;
#pragma unroll
    for (int o = 16; o; o >>= 1) q += __shfl_xor_sync(0xffffffffu, q, o);
    if (lane == 0) red[w] = q;
    __syncthreads();
    float tq = 0.f;
#pragma unroll
    for (int i = 0; i < 8; i++) tq += red[i];
    float var = tq * (1.f / 256.f);
    float o = d * rsqrtf(var + 1e-5f) * g1[tid] + bt1[tid];
    h1[(size_t)row * 256 + tid] = fmaxf(o, 0.f);
}

__device__ __forceinline__ void block_reduce_add_double(double v, double* gout)
{
    int lane = threadIdx.x & 31, w = threadIdx.x >> 5;
#pragma unroll
    for (int o = 16; o; o >>= 1) v += __shfl_xor_sync(0xffffffffu, v, o);
    __shared__ double s[8];
    if (lane == 0) s[w] = v;
    __syncthreads();
    if (threadIdx.x == 0) {
        double t = 0.0;
        int nw = (blockDim.x + 31) >> 5;
        for (int i = 0; i < nw; i++) t += s[i];
        atomicAdd(gout, t);
    }
}

// ---------------- z = mu + eps*exp(0.5*lv);  kl term accumulation ----------------
__global__ __launch_bounds__(256) void z_kl_kernel(
    const float* __restrict__ mulv, const float* __restrict__ eps,
    const float* __restrict__ bmu, const float* __restrict__ blv,
    float* __restrict__ z, double* __restrict__ acc)
{
    int idx = blockIdx.x * blockDim.x + threadIdx.x;
    float local = 0.f;
    if (idx < Nn * ZF) {
        int n = idx >> 6, j = idx & 63;
        float mu = mulv[(size_t)n * 128 + j] + bmu[j];
        float lv = mulv[(size_t)n * 128 + 64 + j] + blv[j];
        z[idx] = mu + eps[idx] * expf(0.5f * lv);
        local = 1.f + lv - mu * mu - expf(lv);
    }
    block_reduce_add_double((double)local, acc + 1);
}

__global__ void deg_kernel(const int* __restrict__ pd, int* __restrict__ deg)
{
    int e = blockIdx.x * blockDim.x + threadIdx.x;
    if (e < EP) atomicAdd(&deg[pd[e]], 1);
}

__global__ void dis_kernel(const int* __restrict__ deg, float* __restrict__ dis)
{
    int n = blockIdx.x * blockDim.x + threadIdx.x;
    if (n < Nn) dis[n] = rsqrtf((float)(deg[n] + 1));
}

// ---------------- normalized scatter for decoder GCN (v4) ----------------
// 16 float4 per edge (64 floats). One thread = one float4.
__global__ __launch_bounds__(256) void scatter_norm_v4_kernel(
    const float4* __restrict__ m, const int* __restrict__ ps,
    const int* __restrict__ pd, const float* __restrict__ dis,
    float* __restrict__ out)
{
    int idx = blockIdx.x * blockDim.x + threadIdx.x;
    if (idx >= EP * 16) return;
    int e = idx >> 4, f = idx & 15;
    int s = ps[e], d = pd[e];
    float nrm = dis[s] * dis[d];
    float4 v = m[((size_t)s << 4) + f];
    v.x *= nrm; v.y *= nrm; v.z *= nrm; v.w *= nrm;
    red_add_v4(out + ((((size_t)d << 4) + f) << 2), v);
}

// ---------------- decoder finalize: self-loop + bias + relu (in place OK) ----------------
__global__ __launch_bounds__(256) void dec_fin_v4_kernel(
    const float4* aggv, const float4* __restrict__ m,
    const float* __restrict__ dis, const float4* __restrict__ bd, float4* outp)
{
    int idx = blockIdx.x * blockDim.x + threadIdx.x;
    if (idx >= Nn * 16) return;
    int n = idx >> 4, j = idx & 15;
    float di = dis[n];
    float sl = di * di;
    float4 a = aggv[idx], mm = m[idx], b = bd[j];
    float4 r;
    r.x = fmaxf(a.x + mm.x * sl + b.x, 0.f);
    r.y = fmaxf(a.y + mm.y * sl + b.y, 0.f);
    r.z = fmaxf(a.z + mm.z * sl + b.z, 0.f);
    r.w = fmaxf(a.w + mm.w * sl + b.w, 0.f);
    outp[idx] = r;
}

// ---------------- fused edge decoder + BCE loss ----------------
__global__ __launch_bounds__(256) void edge_loss_kernel(
    const float* __restrict__ h, const float* __restrict__ A12,
    const float* __restrict__ Wa, const float* __restrict__ ba,
    const float* __restrict__ Wb, const float* __restrict__ bb,
    const float* __restrict__ tau,
    const int* __restrict__ pu, const int* __restrict__ pv,
    const int* __restrict__ nu, const int* __restrict__ nv,
    double* __restrict__ acc)
{
    extern __shared__ float sm[];
    float* sW = sm;                 // [128][64]   = 8192
    float* sF = sW + 8192;          // [128][32]   = 4096 (k-major, edge-fast)
    float* sHU = sF + 4096;         // [32][65]    = 2080
    float* sHV = sHU + 2080;        // 2080
    float* sLogit = sHV + 2080;     // 32
    int* sU = (int*)(sLogit + 32);  // 32
    int* sV = sU + 32;              // 32

    int tid = threadIdx.x;
    int lane = tid & 31, wid = tid >> 5;
    int j = tid & 63, erow = tid >> 6;

    const float* W34 = Wa + 128 * 64;
    for (int i = tid; i < 8192; i += 256) sW[i] = W34[i];

    float tc = fmaxf(tau[0], 1e-4f);
    float invt = 1.0f / tc;
    float bbv = bb[0];
    float baj = ba[j];
    float wbj = Wb[j];
    const float pw = (float)ENEG / (float)EP;
    double dsum = 0.0;

    int nTiles = ETOT / 32;  // 22500, exact
    for (int tile = blockIdx.x; tile < nTiles; tile += gridDim.x) {
        __syncthreads();
        if (tid < 32) {
            int ge = tile * 32 + tid;
            int u, v;
            if (ge < EP) { u = pu[ge]; v = pv[ge]; }
            else         { u = nu[ge - EP]; v = nv[ge - EP]; }
            sU[tid] = u; sV[tid] = v;
            sLogit[tid] = 0.f;
        }
        __syncthreads();
#pragma unroll
        for (int ee = 0; ee < 4; ee++) {
            int e = wid * 4 + ee;
            int u = sU[e], v = sV[e];
            sHU[e * 65 + lane]      = h[(size_t)u * 64 + lane];
            sHU[e * 65 + 32 + lane] = h[(size_t)u * 64 + 32 + lane];
            sHV[e * 65 + lane]      = h[(size_t)v * 64 + lane];
            sHV[e * 65 + 32 + lane] = h[(size_t)v * 64 + 32 + lane];
        }
        __syncthreads();
#pragma unroll
        for (int p = 0; p < 8; p++) {
            int i = tid + p * 256;
            int e = i & 31, f = i >> 5;
            float hu = sHU[e * 65 + f], hv = sHV[e * 65 + f];
            sF[f * 32 + e]        = fabsf(hu - hv);
            sF[(64 + f) * 32 + e] = hu * hv;
        }
        __syncthreads();
        ull a0 = 0, a1 = 0, a2 = 0, a3 = 0;
        const float* fbase = sF + erow * 8;
#pragma unroll 4
        for (int k = 0; k < 128; k++) {
            float w = sW[k * 64 + j];
            ull w2;
            asm("mov.b64 %0, {%1, %1};" : "=l"(w2) : "f"(w));
            ulonglong2 fA = *(const ulonglong2*)(fbase + k * 32);
            ulonglong2 fB = *(const ulonglong2*)(fbase + k * 32 + 4);
            FMA2(a0, fA.x, w2); FMA2(a1, fA.y, w2);
            FMA2(a2, fB.x, w2); FMA2(a3, fB.y, w2);
        }
        union { ull u; float f[2]; } c0, c1, c2, c3;
        c0.u = a0; c1.u = a1; c2.u = a2; c3.u = a3;
        float vals[8] = {c0.f[0], c0.f[1], c1.f[0], c1.f[1],
                         c2.f[0], c2.f[1], c3.f[0], c3.f[1]};
#pragma unroll
        for (int q = 0; q < 8; q++) {
            int e = erow * 8 + q;
            int u = sU[e], v = sV[e];
            float t = vals[q] + A12[(size_t)u * 128 + j] + A12[(size_t)v * 128 + 64 + j] + baj;
            float r = fmaxf(t, 0.f) * wbj;
#pragma unroll
            for (int o = 16; o; o >>= 1) r += __shfl_xor_sync(0xffffffffu, r, o);
            if (lane == 0) atomicAdd(&sLogit[e], r);
        }
        __syncthreads();
        if (tid < 32) {
            float l = (sLogit[tid] + bbv) * invt;
            int ge = tile * 32 + tid;
            float term;
            if (ge < EP) {
                float ls = fminf(l, 0.f) - log1pf(expf(-fabsf(l)));
                term = pw * ls;
            } else {
                float ls = fminf(-l, 0.f) - log1pf(expf(-fabsf(l)));
                term = ls;
            }
            dsum += (double)term;
        }
    }
    __syncthreads();
#pragma unroll
    for (int o = 16; o; o >>= 1) dsum += __shfl_xor_sync(0xffffffffu, dsum, o);
    __shared__ double sred[8];
    if (lane == 0) sred[wid] = dsum;
    __syncthreads();
    if (tid == 0) {
        double t = 0.0;
        for (int i = 0; i < 8; i++) t += sred[i];
        atomicAdd(acc, t);
    }
}

__global__ void finalize_kernel(const double* __restrict__ acc, float* __restrict__ out, int n)
{
    double recon = -acc[0] / (double)ETOT;
    double kl = -0.5 * acc[1] / ((double)Nn * 64.0);
    if (n >= 3) {
        out[0] = (float)(recon + kl);
        out[1] = (float)recon;
        out[2] = (float)kl;
    } else {
        out[0] = (float)(recon + kl);
    }
}

// ---------------- launch ----------------
extern "C" void kernel_launch(void* const* d_in, const int* in_sizes, int n_in,
                              void* d_out, int out_size)
{
    const float* x   = (const float*)d_in[0];
    const float* eps = (const float*)d_in[1];
    const int* edge_index = (const int*)d_in[2];
    const int* pos_edge   = (const int*)d_in[3];
    const int* neg_edge   = (const int*)d_in[4];
    const float* W1  = (const float*)d_in[5];
    const float* b1  = (const float*)d_in[6];
    const float* g1  = (const float*)d_in[7];
    const float* bt1 = (const float*)d_in[8];
    const float* Wmu = (const float*)d_in[9];
    const float* bmu = (const float*)d_in[10];
    const float* Wlv = (const float*)d_in[11];
    const float* blv = (const float*)d_in[12];
    const float* Wd1 = (const float*)d_in[13];
    const float* bd1 = (const float*)d_in[14];
    const float* Wd2 = (const float*)d_in[15];
    const float* bd2 = (const float*)d_in[16];
    const float* Wa  = (const float*)d_in[17];
    const float* ba  = (const float*)d_in[18];
    const float* Wb  = (const float*)d_in[19];
    const float* bb  = (const float*)d_in[20];
    const float* tau = (const float*)d_in[21];

    float *p_m, *p_agg, *p_h1, *p_tmulv, *p_mulv, *p_z, *p_md, *p_hd, *p_hd2, *p_A12, *p_dis;
    int* p_deg;
    double* p_acc;
    cudaGetSymbolAddress((void**)&p_m, g_m);
    cudaGetSymbolAddress((void**)&p_agg, g_agg);
    cudaGetSymbolAddress((void**)&p_h1, g_h1);
    cudaGetSymbolAddress((void**)&p_tmulv, g_tmulv);
    cudaGetSymbolAddress((void**)&p_mulv, g_mulv);
    cudaGetSymbolAddress((void**)&p_z, g_z);
    cudaGetSymbolAddress((void**)&p_md, g_md);
    cudaGetSymbolAddress((void**)&p_hd, g_hd);
    cudaGetSymbolAddress((void**)&p_hd2, g_hd2);
    cudaGetSymbolAddress((void**)&p_A12, g_A12);
    cudaGetSymbolAddress((void**)&p_dis, g_dis);
    cudaGetSymbolAddress((void**)&p_deg, g_deg);
    cudaGetSymbolAddress((void**)&p_acc, g_acc);

    const int* src = edge_index;
    const int* dst = edge_index + E2;
    const int* pu = pos_edge;
    const int* pv = pos_edge + EP;
    const int* nu = neg_edge;
    const int* nv = neg_edge + ENEG;

    // ---- encoder layer 1 ----
    cudaMemsetAsync(p_agg, 0, sizeof(float) * (size_t)Nn * HIDF);
    {
        dim3 g(4, (Nn + 63) / 64);
        sgemm_kernel<<<g, 256>>>(x, W1, p_m, Nn, 256, 256, 256, 0);
    }
    {
        int total = E2 * 64;  // 64 float4 per edge
        scatter_add_v4_kernel<<<(total + 255) / 256, 256>>>(
            (const float4*)p_m, src, dst, p_agg, E2, 6);
    }
    ln_relu_kernel<<<Nn, 256>>>(p_agg, b1, g1, bt1, p_h1);

    // ---- mu / logvar ----
    {
        dim3 g(1, (Nn + 63) / 64);
        sgemm_kernel<<<g, 256>>>(p_h1, Wmu, p_tmulv, Nn, 64, 256, 128, 0);
        sgemm_kernel<<<g, 256>>>(p_h1, Wlv, p_tmulv, Nn, 64, 256, 128, 64);
    }
    cudaMemsetAsync(p_mulv, 0, sizeof(float) * (size_t)Nn * 128);
    {
        int total = E2 * 32;  // 32 float4 per edge
        scatter_add_v4_kernel<<<(total + 255) / 256, 256>>>(
            (const float4*)p_tmulv, src, dst, p_mulv, E2, 5);
    }
    cudaMemsetAsync(p_acc, 0, 2 * sizeof(double));
    z_kl_kernel<<<(Nn * 64 + 255) / 256, 256>>>(p_mulv, eps, bmu, blv, p_z, p_acc);

    // ---- decoder normalization ----
    cudaMemsetAsync(p_deg, 0, sizeof(int) * Nn);
    deg_kernel<<<(EP + 255) / 256, 256>>>(pv, p_deg);
    dis_kernel<<<(Nn + 255) / 256, 256>>>(p_deg, p_dis);

    // ---- decoder GCN pass 1 ----
    {
        dim3 g(1, (Nn + 63) / 64);
        sgemm_kernel<<<g, 256>>>(p_z, Wd1, p_md, Nn, 64, 64, 64, 0);
    }
    cudaMemsetAsync(p_hd, 0, sizeof(float) * (size_t)Nn * 64);
    scatter_norm_v4_kernel<<<(EP * 16 + 255) / 256, 256>>>(
        (const float4*)p_md, pu, pv, p_dis, p_hd);
    dec_fin_v4_kernel<<<(Nn * 16 + 255) / 256, 256>>>(
        (const float4*)p_hd, (const float4*)p_md, p_dis, (const float4*)bd1, (float4*)p_hd);

    // ---- decoder GCN pass 2 ----
    {
        dim3 g(1, (Nn + 63) / 64);
        sgemm_kernel<<<g, 256>>>(p_hd, Wd2, p_md, Nn, 64, 64, 64, 0);
    }
    cudaMemsetAsync(p_hd2, 0, sizeof(float) * (size_t)Nn * 64);
    scatter_norm_v4_kernel<<<(EP * 16 + 255) / 256, 256>>>(
        (const float4*)p_md, pu, pv, p_dis, p_hd2);
    dec_fin_v4_kernel<<<(Nn * 16 + 255) / 256, 256>>>(
        (const float4*)p_hd2, (const float4*)p_md, p_dis, (const float4*)bd2, (float4*)p_hd2);

    // ---- per-node precompute of hu@Wa1, hv@Wa2 ----
    {
        dim3 g(1, (Nn + 63) / 64);
        sgemm_kernel<<<g, 256>>>(p_hd2, Wa, p_A12, Nn, 64, 64, 128, 0);
        sgemm_kernel<<<g, 256>>>(p_hd2, Wa + 64 * 64, p_A12, Nn, 64, 64, 128, 64);
    }

    // ---- fused edge decoder + loss ----
    {
        int smem = (8192 + 4096 + 2080 + 2080 + 32) * 4 + 64 * 4;
        cudaFuncSetAttribute(edge_loss_kernel, cudaFuncAttributeMaxDynamicSharedMemorySize, smem);
        edge_loss_kernel<<<444, 256, smem>>>(p_hd2, p_A12, Wa, ba, Wb, bb, tau,
                                             pu, pv, nu, nv, p_acc);
    }

    finalize_kernel<<<1, 1>>>(p_acc, (float*)d_out, out_size);

    (void)in_sizes; (void)n_in;
}

// round 5
// speedup vs baseline: 1.3362x; 1.1179x over previous
#include <cuda_runtime.h>
#include <math.h>

#define Nn    20000
#define HIDF  256
#define ZF    64
#define EP    120000
#define E2    240000
#define ENEG  600000
#define ETOT  720000

typedef unsigned long long ull;

// ---------------- scratch (static device globals; no allocation) ----------------
__device__ __align__(16) float g_m[Nn * HIDF];        // x@W1
__device__ __align__(16) float g_agg[Nn * HIDF];      // scatter target layer1
__device__ __align__(16) float g_h1[Nn * HIDF];       // post LN+relu
__device__ __align__(16) float g_tmulv[Nn * 128];     // [h1@Wmu | h1@Wlv]
__device__ __align__(16) float g_mulv[Nn * 128];      // scattered
__device__ __align__(16) float g_z[Nn * ZF];
__device__ __align__(16) float g_md[Nn * ZF];         // decoder gemm out (reused both passes)
__device__ __align__(16) float g_hd[Nn * ZF];         // decoder layer1 agg / h
__device__ __align__(16) float g_hd2[Nn * ZF];        // decoder layer2 agg / h
__device__ __align__(16) float g_A12[Nn * 128];       // [h@Wa1 | h@Wa2]
__device__ float g_dis[Nn];
__device__ int   g_deg[Nn];
__device__ double g_acc[2];             // [recon_sum, kl_sum]

#define FMA2(c, a, b) asm("fma.rn.f32x2 %0, %1, %2, %0;" : "+l"(c) : "l"(a), "l"(b))

__device__ __forceinline__ void red_add_v4(float* p, float4 v)
{
    asm volatile("red.global.add.v4.f32 [%0], {%1, %2, %3, %4};"
                 :: "l"(p), "f"(v.x), "f"(v.y), "f"(v.z), "f"(v.w) : "memory");
}

// ---------------- generic SGEMM: C[M,ldc](+coff) = A[M,K] @ B[K,Ncols] ----------------
__global__ __launch_bounds__(256) void sgemm_kernel(
    const float* __restrict__ A, const float* __restrict__ B, float* __restrict__ C,
    int M, int Ncols, int K, int ldc, int coff)
{
    __shared__ float As2[16][128];   // A value duplicated in pairs -> LDS.64 gives {a,a}
    __shared__ float Bs[16][64];
    int tid = threadIdx.x;
    int m0 = blockIdx.y * 64;
    int n0 = blockIdx.x * 64;
    int ty = tid >> 4, tx = tid & 15;
    int am = tid >> 2, ak = (tid & 3) * 4;
    int bk = tid >> 4, bn = (tid & 15) * 4;

    ull acc[4][2];
#pragma unroll
    for (int i = 0; i < 4; i++) { acc[i][0] = 0ull; acc[i][1] = 0ull; }

    for (int k0 = 0; k0 < K; k0 += 16) {
        float4 va = make_float4(0.f, 0.f, 0.f, 0.f);
        int gm = m0 + am;
        if (gm < M) va = *(const float4*)(A + (size_t)gm * K + k0 + ak);
        As2[ak + 0][2 * am] = va.x; As2[ak + 0][2 * am + 1] = va.x;
        As2[ak + 1][2 * am] = va.y; As2[ak + 1][2 * am + 1] = va.y;
        As2[ak + 2][2 * am] = va.z; As2[ak + 2][2 * am + 1] = va.z;
        As2[ak + 3][2 * am] = va.w; As2[ak + 3][2 * am + 1] = va.w;
        *(float4*)&Bs[bk][bn] = *(const float4*)(B + (size_t)(k0 + bk) * Ncols + n0 + bn);
        __syncthreads();
#pragma unroll
        for (int kk = 0; kk < 16; kk++) {
            ull a0 = *(const ull*)&As2[kk][(ty * 4 + 0) * 2];
            ull a1 = *(const ull*)&As2[kk][(ty * 4 + 1) * 2];
            ull a2 = *(const ull*)&As2[kk][(ty * 4 + 2) * 2];
            ull a3 = *(const ull*)&As2[kk][(ty * 4 + 3) * 2];
            union { float4 f4; ull u[2]; } bu;
            bu.f4 = *(const float4*)&Bs[kk][tx * 4];
            FMA2(acc[0][0], a0, bu.u[0]); FMA2(acc[0][1], a0, bu.u[1]);
            FMA2(acc[1][0], a1, bu.u[0]); FMA2(acc[1][1], a1, bu.u[1]);
            FMA2(acc[2][0], a2, bu.u[0]); FMA2(acc[2][1], a2, bu.u[1]);
            FMA2(acc[3][0], a3, bu.u[0]); FMA2(acc[3][1], a3, bu.u[1]);
        }
        __syncthreads();
    }
#pragma unroll
    for (int i = 0; i < 4; i++) {
        int gm = m0 + ty * 4 + i;
        if (gm < M) {
            union { ull u[2]; float f[4]; } r;
            r.u[0] = acc[i][0]; r.u[1] = acc[i][1];
            *(float4*)(C + (size_t)gm * ldc + coff + n0 + tx * 4) =
                make_float4(r.f[0], r.f[1], r.f[2], r.f[3]);
        }
    }
}

// ---------------- vectorized scatter add ----------------
__global__ __launch_bounds__(256) void scatter_add_v4_kernel(
    const float4* __restrict__ m, const int* __restrict__ src,
    const int* __restrict__ dst, float* __restrict__ out, int nE, int lgF4)
{
    int idx = blockIdx.x * blockDim.x + threadIdx.x;
    int total = nE << lgF4;
    if (idx >= total) return;
    int e = idx >> lgF4;
    int f = idx & ((1 << lgF4) - 1);
    float4 v = m[((size_t)src[e] << lgF4) + f];
    red_add_v4(out + ((((size_t)dst[e] << lgF4) + f) << 2), v);
}

// ---------------- LayerNorm + bias + relu (row of 256) ----------------
__global__ __launch_bounds__(256) void ln_relu_kernel(
    const float* __restrict__ agg, const float* __restrict__ b1,
    const float* __restrict__ g1, const float* __restrict__ bt1, float* __restrict__ h1)
{
    int row = blockIdx.x;
    int tid = threadIdx.x;
    int lane = tid & 31, w = tid >> 5;
    float v = agg[(size_t)row * 256 + tid] + b1[tid];
    __shared__ float red[8];
    float s = v;
#pragma unroll
    for (int o = 16; o; o >>= 1) s += __shfl_xor_sync(0xffffffffu, s, o);
    if (lane == 0) red[w] = s;
    __syncthreads();
    float tot = 0.f;
#pragma unroll
    for (int i = 0; i < 8; i++) tot += red[i];
    float mu = tot * (1.f / 256.f);
    __syncthreads();
    float d = v - mu;
    float q = d * d;
#pragma unroll
    for (int o = 16; o; o >>= 1) q += __shfl_xor_sync(0xffffffffu, q, o);
    if (lane == 0) red[w] = q;
    __syncthreads();
    float tq = 0.f;
#pragma unroll
    for (int i = 0; i < 8; i++) tq += red[i];
    float var = tq * (1.f / 256.f);
    float o = d * rsqrtf(var + 1e-5f) * g1[tid] + bt1[tid];
    h1[(size_t)row * 256 + tid] = fmaxf(o, 0.f);
}

__device__ __forceinline__ void block_reduce_add_double(double v, double* gout)
{
    int lane = threadIdx.x & 31, w = threadIdx.x >> 5;
#pragma unroll
    for (int o = 16; o; o >>= 1) v += __shfl_xor_sync(0xffffffffu, v, o);
    __shared__ double s[8];
    if (lane == 0) s[w] = v;
    __syncthreads();
    if (threadIdx.x == 0) {
        double t = 0.0;
        int nw = (blockDim.x + 31) >> 5;
        for (int i = 0; i < nw; i++) t += s[i];
        atomicAdd(gout, t);
    }
}

// ---------------- z = mu + eps*exp(0.5*lv);  kl term accumulation ----------------
__global__ __launch_bounds__(256) void z_kl_kernel(
    const float* __restrict__ mulv, const float* __restrict__ eps,
    const float* __restrict__ bmu, const float* __restrict__ blv,
    float* __restrict__ z, double* __restrict__ acc)
{
    int idx = blockIdx.x * blockDim.x + threadIdx.x;
    float local = 0.f;
    if (idx < Nn * ZF) {
        int n = idx >> 6, j = idx & 63;
        float mu = mulv[(size_t)n * 128 + j] + bmu[j];
        float lv = mulv[(size_t)n * 128 + 64 + j] + blv[j];
        z[idx] = mu + eps[idx] * expf(0.5f * lv);
        local = 1.f + lv - mu * mu - expf(lv);
    }
    block_reduce_add_double((double)local, acc + 1);
}

__global__ void deg_kernel(const int* __restrict__ pd, int* __restrict__ deg)
{
    int e = blockIdx.x * blockDim.x + threadIdx.x;
    if (e < EP) atomicAdd(&deg[pd[e]], 1);
}

__global__ void dis_kernel(const int* __restrict__ deg, float* __restrict__ dis)
{
    int n = blockIdx.x * blockDim.x + threadIdx.x;
    if (n < Nn) dis[n] = rsqrtf((float)(deg[n] + 1));
}

// ---------------- normalized scatter for decoder GCN (v4) ----------------
__global__ __launch_bounds__(256) void scatter_norm_v4_kernel(
    const float4* __restrict__ m, const int* __restrict__ ps,
    const int* __restrict__ pd, const float* __restrict__ dis,
    float* __restrict__ out)
{
    int idx = blockIdx.x * blockDim.x + threadIdx.x;
    if (idx >= EP * 16) return;
    int e = idx >> 4, f = idx & 15;
    int s = ps[e], d = pd[e];
    float nrm = dis[s] * dis[d];
    float4 v = m[((size_t)s << 4) + f];
    v.x *= nrm; v.y *= nrm; v.z *= nrm; v.w *= nrm;
    red_add_v4(out + ((((size_t)d << 4) + f) << 2), v);
}

// ---------------- decoder finalize: self-loop + bias + relu ----------------
__global__ __launch_bounds__(256) void dec_fin_v4_kernel(
    const float4* aggv, const float4* __restrict__ m,
    const float* __restrict__ dis, const float4* __restrict__ bd, float4* outp)
{
    int idx = blockIdx.x * blockDim.x + threadIdx.x;
    if (idx >= Nn * 16) return;
    int n = idx >> 4, j = idx & 15;
    float di = dis[n];
    float sl = di * di;
    float4 a = aggv[idx], mm = m[idx], b = bd[j];
    float4 r;
    r.x = fmaxf(a.x + mm.x * sl + b.x, 0.f);
    r.y = fmaxf(a.y + mm.y * sl + b.y, 0.f);
    r.z = fmaxf(a.z + mm.z * sl + b.z, 0.f);
    r.w = fmaxf(a.w + mm.w * sl + b.w, 0.f);
    outp[idx] = r;
}

// ---------------- fused edge decoder + BCE loss (64-edge tiles, 8e x 2c per thread) ----
// warp w owns edges w*8..w*8+7 (all 64 cols via lanes: cols 2*lane, 2*lane+1).
__global__ __launch_bounds__(256) void edge_loss_kernel(
    const float* __restrict__ h, const float* __restrict__ A12,
    const float* __restrict__ Wa, const float* __restrict__ ba,
    const float* __restrict__ Wb, const float* __restrict__ bb,
    const float* __restrict__ tau,
    const int* __restrict__ pu, const int* __restrict__ pv,
    const int* __restrict__ nu, const int* __restrict__ nv,
    double* __restrict__ acc)
{
    extern __shared__ float sm[];
    float* sW = sm;                   // [128][64]  = 8192 floats
    float* sF = sW + 8192;            // [128][64]  = 8192 (k-major, edge-fast)
    float* sHU = sF + 8192;           // [64][65]   = 4160
    float* sHV = sHU + 4160;          // 4160
    int* sU = (int*)(sHV + 4160);     // 64
    int* sV = sU + 64;                // 64

    int tid = threadIdx.x;
    int lane = tid & 31, wid = tid >> 5;

    const float* W34 = Wa + 128 * 64;
    for (int i = tid; i < 8192; i += 256) sW[i] = W34[i];

    float tc = fmaxf(tau[0], 1e-4f);
    float invt = 1.0f / tc;
    float bbv = bb[0];
    float2 ba2 = ((const float2*)ba)[lane];
    float2 wb2 = ((const float2*)Wb)[lane];
    const float pw = (float)ENEG / (float)EP;
    double dsum = 0.0;

    int nTiles = ETOT / 64;  // 11250, exact; EP % 64 == 0 too
    for (int tile = blockIdx.x; tile < nTiles; tile += gridDim.x) {
        __syncthreads();  // previous tile fully consumed (also orders sW on iter 0)
        if (tid < 64) {
            int ge = tile * 64 + tid;
            int u, v;
            if (ge < EP) { u = pu[ge]; v = pv[ge]; }
            else         { u = nu[ge - EP]; v = nv[ge - EP]; }
            sU[tid] = u; sV[tid] = v;
        }
        __syncthreads();
        // phase A: coalesced gather of h rows (warp per 8 edges)
#pragma unroll
        for (int ee = 0; ee < 8; ee++) {
            int e = wid * 8 + ee;
            int u = sU[e], v = sV[e];
            sHU[e * 65 + lane]      = h[(size_t)u * 64 + lane];
            sHU[e * 65 + 32 + lane] = h[(size_t)u * 64 + 32 + lane];
            sHV[e * 65 + lane]      = h[(size_t)v * 64 + lane];
            sHV[e * 65 + 32 + lane] = h[(size_t)v * 64 + 32 + lane];
        }
        __syncthreads();
        // phase B: transpose + feature build (conflict-free both sides)
#pragma unroll
        for (int p = 0; p < 16; p++) {
            int i = tid + p * 256;
            int e = i & 63, f = i >> 6;
            float hu = sHU[e * 65 + f], hv = sHV[e * 65 + f];
            sF[f * 64 + e]        = fabsf(hu - hv);
            sF[(64 + f) * 64 + e] = hu * hv;
        }
        __syncthreads();
        // mainloop: 128 k-steps; acc[0..3] = col 2*lane, acc[4..7] = col 2*lane+1
        ull a[8];
#pragma unroll
        for (int i = 0; i < 8; i++) a[i] = 0ull;
        const float* fbase = sF + wid * 8;
#pragma unroll 4
        for (int k = 0; k < 128; k++) {
            float2 w = *(const float2*)&sW[k * 64 + 2 * lane];
            ull w0, w1;
            asm("mov.b64 %0, {%1, %1};" : "=l"(w0) : "f"(w.x));
            asm("mov.b64 %0, {%1, %1};" : "=l"(w1) : "f"(w.y));
            ulonglong2 fA = *(const ulonglong2*)(fbase + k * 64);
            ulonglong2 fB = *(const ulonglong2*)(fbase + k * 64 + 4);
            FMA2(a[0], fA.x, w0); FMA2(a[1], fA.y, w0);
            FMA2(a[2], fB.x, w0); FMA2(a[3], fB.y, w0);
            FMA2(a[4], fA.x, w1); FMA2(a[5], fA.y, w1);
            FMA2(a[6], fB.x, w1); FMA2(a[7], fB.y, w1);
        }
        // epilogue: per edge, + A12 terms + ba, relu, *Wb, warp-reduce over 64 cols
#pragma unroll
        for (int q = 0; q < 8; q++) {
            int e = wid * 8 + q;
            int u = sU[e], v = sV[e];
            union { ull uu; float f[2]; } c0, c1;
            c0.uu = a[q >> 1];          // col 2*lane, edge pair
            c1.uu = a[4 + (q >> 1)];    // col 2*lane+1
            float v0 = c0.f[q & 1];
            float v1 = c1.f[q & 1];
            float2 au = *(const float2*)&A12[(size_t)u * 128 + 2 * lane];
            float2 av = *(const float2*)&A12[(size_t)v * 128 + 64 + 2 * lane];
            float t0 = v0 + au.x + av.x + ba2.x;
            float t1 = v1 + au.y + av.y + ba2.y;
            float r = fmaxf(t0, 0.f) * wb2.x + fmaxf(t1, 0.f) * wb2.y;
#pragma unroll
            for (int o = 16; o; o >>= 1) r += __shfl_xor_sync(0xffffffffu, r, o);
            if (lane == 0) {
                float l = (r + bbv) * invt;
                int ge = tile * 64 + e;
                float term;
                if (ge < EP) {
                    float ls = fminf(l, 0.f) - log1pf(expf(-fabsf(l)));
                    term = pw * ls;
                } else {
                    float ls = fminf(-l, 0.f) - log1pf(expf(-fabsf(l)));
                    term = ls;
                }
                dsum += (double)term;
            }
        }
    }
#pragma unroll
    for (int o = 16; o; o >>= 1) dsum += __shfl_xor_sync(0xffffffffu, dsum, o);
    __shared__ double sred[8];
    if (lane == 0) sred[wid] = dsum;
    __syncthreads();
    if (tid == 0) {
        double t = 0.0;
        for (int i = 0; i < 8; i++) t += sred[i];
        atomicAdd(acc, t);
    }
}

__global__ void finalize_kernel(const double* __restrict__ acc, float* __restrict__ out, int n)
{
    double recon = -acc[0] / (double)ETOT;
    double kl = -0.5 * acc[1] / ((double)Nn * 64.0);
    if (n >= 3) {
        out[0] = (float)(recon + kl);
        out[1] = (float)recon;
        out[2] = (float)kl;
    } else {
        out[0] = (float)(recon + kl);
    }
}

// ---------------- launch ----------------
extern "C" void kernel_launch(void* const* d_in, const int* in_sizes, int n_in,
                              void* d_out, int out_size)
{
    const float* x   = (const float*)d_in[0];
    const float* eps = (const float*)d_in[1];
    const int* edge_index = (const int*)d_in[2];
    const int* pos_edge   = (const int*)d_in[3];
    const int* neg_edge   = (const int*)d_in[4];
    const float* W1  = (const float*)d_in[5];
    const float* b1  = (const float*)d_in[6];
    const float* g1  = (const float*)d_in[7];
    const float* bt1 = (const float*)d_in[8];
    const float* Wmu = (const float*)d_in[9];
    const float* bmu = (const float*)d_in[10];
    const float* Wlv = (const float*)d_in[11];
    const float* blv = (const float*)d_in[12];
    const float* Wd1 = (const float*)d_in[13];
    const float* bd1 = (const float*)d_in[14];
    const float* Wd2 = (const float*)d_in[15];
    const float* bd2 = (const float*)d_in[16];
    const float* Wa  = (const float*)d_in[17];
    const float* ba  = (const float*)d_in[18];
    const float* Wb  = (const float*)d_in[19];
    const float* bb  = (const float*)d_in[20];
    const float* tau = (const float*)d_in[21];

    float *p_m, *p_agg, *p_h1, *p_tmulv, *p_mulv, *p_z, *p_md, *p_hd, *p_hd2, *p_A12, *p_dis;
    int* p_deg;
    double* p_acc;
    cudaGetSymbolAddress((void**)&p_m, g_m);
    cudaGetSymbolAddress((void**)&p_agg, g_agg);
    cudaGetSymbolAddress((void**)&p_h1, g_h1);
    cudaGetSymbolAddress((void**)&p_tmulv, g_tmulv);
    cudaGetSymbolAddress((void**)&p_mulv, g_mulv);
    cudaGetSymbolAddress((void**)&p_z, g_z);
    cudaGetSymbolAddress((void**)&p_md, g_md);
    cudaGetSymbolAddress((void**)&p_hd, g_hd);
    cudaGetSymbolAddress((void**)&p_hd2, g_hd2);
    cudaGetSymbolAddress((void**)&p_A12, g_A12);
    cudaGetSymbolAddress((void**)&p_dis, g_dis);
    cudaGetSymbolAddress((void**)&p_deg, g_deg);
    cudaGetSymbolAddress((void**)&p_acc, g_acc);

    const int* src = edge_index;
    const int* dst = edge_index + E2;
    const int* pu = pos_edge;
    const int* pv = pos_edge + EP;
    const int* nu = neg_edge;
    const int* nv = neg_edge + ENEG;

    // ---- encoder layer 1 ----
    cudaMemsetAsync(p_agg, 0, sizeof(float) * (size_t)Nn * HIDF);
    {
        dim3 g(4, (Nn + 63) / 64);
        sgemm_kernel<<<g, 256>>>(x, W1, p_m, Nn, 256, 256, 256, 0);
    }
    {
        int total = E2 * 64;
        scatter_add_v4_kernel<<<(total + 255) / 256, 256>>>(
            (const float4*)p_m, src, dst, p_agg, E2, 6);
    }
    ln_relu_kernel<<<Nn, 256>>>(p_agg, b1, g1, bt1, p_h1);

    // ---- mu / logvar ----
    {
        dim3 g(1, (Nn + 63) / 64);
        sgemm_kernel<<<g, 256>>>(p_h1, Wmu, p_tmulv, Nn, 64, 256, 128, 0);
        sgemm_kernel<<<g, 256>>>(p_h1, Wlv, p_tmulv, Nn, 64, 256, 128, 64);
    }
    cudaMemsetAsync(p_mulv, 0, sizeof(float) * (size_t)Nn * 128);
    {
        int total = E2 * 32;
        scatter_add_v4_kernel<<<(total + 255) / 256, 256>>>(
            (const float4*)p_tmulv, src, dst, p_mulv, E2, 5);
    }
    cudaMemsetAsync(p_acc, 0, 2 * sizeof(double));
    z_kl_kernel<<<(Nn * 64 + 255) / 256, 256>>>(p_mulv, eps, bmu, blv, p_z, p_acc);

    // ---- decoder normalization ----
    cudaMemsetAsync(p_deg, 0, sizeof(int) * Nn);
    deg_kernel<<<(EP + 255) / 256, 256>>>(pv, p_deg);
    dis_kernel<<<(Nn + 255) / 256, 256>>>(p_deg, p_dis);

    // ---- decoder GCN pass 1 ----
    {
        dim3 g(1, (Nn + 63) / 64);
        sgemm_kernel<<<g, 256>>>(p_z, Wd1, p_md, Nn, 64, 64, 64, 0);
    }
    cudaMemsetAsync(p_hd, 0, sizeof(float) * (size_t)Nn * 64);
    scatter_norm_v4_kernel<<<(EP * 16 + 255) / 256, 256>>>(
        (const float4*)p_md, pu, pv, p_dis, p_hd);
    dec_fin_v4_kernel<<<(Nn * 16 + 255) / 256, 256>>>(
        (const float4*)p_hd, (const float4*)p_md, p_dis, (const float4*)bd1, (float4*)p_hd);

    // ---- decoder GCN pass 2 ----
    {
        dim3 g(1, (Nn + 63) / 64);
        sgemm_kernel<<<g, 256>>>(p_hd, Wd2, p_md, Nn, 64, 64, 64, 0);
    }
    cudaMemsetAsync(p_hd2, 0, sizeof(float) * (size_t)Nn * 64);
    scatter_norm_v4_kernel<<<(EP * 16 + 255) / 256, 256>>>(
        (const float4*)p_md, pu, pv, p_dis, p_hd2);
    dec_fin_v4_kernel<<<(Nn * 16 + 255) / 256, 256>>>(
        (const float4*)p_hd2, (const float4*)p_md, p_dis, (const float4*)bd2, (float4*)p_hd2);

    // ---- per-node precompute of hu@Wa1, hv@Wa2 ----
    {
        dim3 g(1, (Nn + 63) / 64);
        sgemm_kernel<<<g, 256>>>(p_hd2, Wa, p_A12, Nn, 64, 64, 128, 0);
        sgemm_kernel<<<g, 256>>>(p_hd2, Wa + 64 * 64, p_A12, Nn, 64, 64, 128, 64);
    }

    // ---- fused edge decoder + loss ----
    {
        int smem = (8192 + 8192 + 4160 + 4160) * 4 + 128 * 4;   // 99328 B
        cudaFuncSetAttribute(edge_loss_kernel, cudaFuncAttributeMaxDynamicSharedMemorySize, smem);
        edge_loss_kernel<<<296, 256, smem>>>(p_hd2, p_A12, Wa, ba, Wb, bb, tau,
                                             pu, pv, nu, nv, p_acc);
    }

    finalize_kernel<<<1, 1>>>(p_acc, (float*)d_out, out_size);

    (void)in_sizes; (void)n_in;
}

// round 6
// speedup vs baseline: 1.4555x; 1.0893x over previous
#include <cuda_runtime.h>
#include <math.h>

#define Nn    20000
#define HIDF  256
#define ZF    64
#define EP    120000
#define E2    240000
#define ENEG  600000
#define ETOT  720000

typedef unsigned long long ull;

// ---------------- scratch (static device globals; no allocation) ----------------
__device__ __align__(16) float g_m[Nn * HIDF];        // x@W1
__device__ __align__(16) float g_agg[Nn * HIDF];      // scatter target layer1
__device__ __align__(16) float g_h1[Nn * HIDF];       // post LN+relu
__device__ __align__(16) float g_tmulv[Nn * 128];     // [h1@Wmu | h1@Wlv]
__device__ __align__(16) float g_mulv[Nn * 128];      // scattered
__device__ __align__(16) float g_z[Nn * ZF];
__device__ __align__(16) float g_md[Nn * ZF];         // decoder gemm out
__device__ __align__(16) float g_hd[Nn * ZF];         // decoder layer1 agg / h
__device__ __align__(16) float g_hd2[Nn * ZF];        // decoder layer2 agg / h
__device__ __align__(16) float g_A12[Nn * 128];       // [h@Wa1 | h@Wa2]
__device__ __align__(16) float g_Wcat[256 * 128];     // packed weight concat
__device__ float g_dis[Nn];
__device__ __align__(16) int g_deg[Nn];
__device__ double g_acc[2];             // [recon_sum, kl_sum]

#define FMA2(c, a, b) asm("fma.rn.f32x2 %0, %1, %2, %0;" : "+l"(c) : "l"(a), "l"(b))

__device__ __forceinline__ void red_add_v4(float* p, float4 v)
{
    asm volatile("red.global.add.v4.f32 [%0], {%1, %2, %3, %4};"
                 :: "l"(p), "f"(v.x), "f"(v.y), "f"(v.z), "f"(v.w) : "memory");
}

// ---------------- fused zero of all scatter targets + accumulators ----------------
__global__ __launch_bounds__(256) void zero_kernel(
    float4* a, int na, float4* b, int nb, float4* c, int nc,
    float4* d, int nd, float4* e, int ne, double* acc)
{
    long idx = (long)blockIdx.x * blockDim.x + threadIdx.x;
    float4 zz = make_float4(0.f, 0.f, 0.f, 0.f);
    if (idx < na) { a[idx] = zz; }
    else {
        long i = idx - na;
        if (i < nb) { b[i] = zz; }
        else {
            i -= nb;
            if (i < nc) { c[i] = zz; }
            else {
                i -= nc;
                if (i < nd) { d[i] = zz; }
                else {
                    i -= nd;
                    if (i < ne) e[i] = zz;
                }
            }
        }
    }
    if (idx < 2) acc[idx] = 0.0;
}

// ---------------- weight pack: out[k][0:64]=A[k][:], out[k][64:128]=B[k][:] ------
__global__ __launch_bounds__(256) void pack2_kernel(
    const float* __restrict__ A, const float* __restrict__ B,
    float* __restrict__ out, int K)
{
    int idx = blockIdx.x * blockDim.x + threadIdx.x;
    if (idx >= K * 64) return;
    int k = idx >> 6, j = idx & 63;
    out[k * 128 + j]      = A[k * 64 + j];
    out[k * 128 + 64 + j] = B[k * 64 + j];
}

// ---------------- SGEMM BM=64: C[M,ldc](+coff) = A[M,K] @ B[K,Ncols] ----------------
__global__ __launch_bounds__(256) void sgemm_kernel(
    const float* __restrict__ A, const float* __restrict__ B, float* __restrict__ C,
    int M, int Ncols, int K, int ldc, int coff)
{
    __shared__ float As2[16][128];
    __shared__ float Bs[16][64];
    int tid = threadIdx.x;
    int m0 = blockIdx.y * 64;
    int n0 = blockIdx.x * 64;
    int ty = tid >> 4, tx = tid & 15;
    int am = tid >> 2, ak = (tid & 3) * 4;
    int bk = tid >> 4, bn = (tid & 15) * 4;

    ull acc[4][2];
#pragma unroll
    for (int i = 0; i < 4; i++) { acc[i][0] = 0ull; acc[i][1] = 0ull; }

    for (int k0 = 0; k0 < K; k0 += 16) {
        float4 va = make_float4(0.f, 0.f, 0.f, 0.f);
        int gm = m0 + am;
        if (gm < M) va = *(const float4*)(A + (size_t)gm * K + k0 + ak);
        As2[ak + 0][2 * am] = va.x; As2[ak + 0][2 * am + 1] = va.x;
        As2[ak + 1][2 * am] = va.y; As2[ak + 1][2 * am + 1] = va.y;
        As2[ak + 2][2 * am] = va.z; As2[ak + 2][2 * am + 1] = va.z;
        As2[ak + 3][2 * am] = va.w; As2[ak + 3][2 * am + 1] = va.w;
        *(float4*)&Bs[bk][bn] = *(const float4*)(B + (size_t)(k0 + bk) * Ncols + n0 + bn);
        __syncthreads();
#pragma unroll
        for (int kk = 0; kk < 16; kk++) {
            ull a0 = *(const ull*)&As2[kk][(ty * 4 + 0) * 2];
            ull a1 = *(const ull*)&As2[kk][(ty * 4 + 1) * 2];
            ull a2 = *(const ull*)&As2[kk][(ty * 4 + 2) * 2];
            ull a3 = *(const ull*)&As2[kk][(ty * 4 + 3) * 2];
            union { float4 f4; ull u[2]; } bu;
            bu.f4 = *(const float4*)&Bs[kk][tx * 4];
            FMA2(acc[0][0], a0, bu.u[0]); FMA2(acc[0][1], a0, bu.u[1]);
            FMA2(acc[1][0], a1, bu.u[0]); FMA2(acc[1][1], a1, bu.u[1]);
            FMA2(acc[2][0], a2, bu.u[0]); FMA2(acc[2][1], a2, bu.u[1]);
            FMA2(acc[3][0], a3, bu.u[0]); FMA2(acc[3][1], a3, bu.u[1]);
        }
        __syncthreads();
    }
#pragma unroll
    for (int i = 0; i < 4; i++) {
        int gm = m0 + ty * 4 + i;
        if (gm < M) {
            union { ull u[2]; float f[4]; } r;
            r.u[0] = acc[i][0]; r.u[1] = acc[i][1];
            *(float4*)(C + (size_t)gm * ldc + coff + n0 + tx * 4) =
                make_float4(r.f[0], r.f[1], r.f[2], r.f[3]);
        }
    }
}

// ---------------- SGEMM BM=32 (128 threads) for tall-skinny, high block count ------
__global__ __launch_bounds__(128) void sgemm32_kernel(
    const float* __restrict__ A, const float* __restrict__ B, float* __restrict__ C,
    int M, int Ncols, int K, int ldc, int coff)
{
    __shared__ float As2[16][64];    // 32 rows duplicated in pairs
    __shared__ float Bs[16][64];
    int tid = threadIdx.x;
    int m0 = blockIdx.y * 32;
    int n0 = blockIdx.x * 64;
    int ty = tid >> 4, tx = tid & 15;       // ty 0..7
    int am = tid >> 2, ak = (tid & 3) * 4;  // am 0..31
    int bk = tid >> 4, bn = (tid & 15) * 4; // bk 0..7 (+8 second row)

    ull acc[4][2];
#pragma unroll
    for (int i = 0; i < 4; i++) { acc[i][0] = 0ull; acc[i][1] = 0ull; }

    for (int k0 = 0; k0 < K; k0 += 16) {
        float4 va = make_float4(0.f, 0.f, 0.f, 0.f);
        int gm = m0 + am;
        if (gm < M) va = *(const float4*)(A + (size_t)gm * K + k0 + ak);
        As2[ak + 0][2 * am] = va.x; As2[ak + 0][2 * am + 1] = va.x;
        As2[ak + 1][2 * am] = va.y; As2[ak + 1][2 * am + 1] = va.y;
        As2[ak + 2][2 * am] = va.z; As2[ak + 2][2 * am + 1] = va.z;
        As2[ak + 3][2 * am] = va.w; As2[ak + 3][2 * am + 1] = va.w;
        *(float4*)&Bs[bk][bn]     = *(const float4*)(B + (size_t)(k0 + bk) * Ncols + n0 + bn);
        *(float4*)&Bs[bk + 8][bn] = *(const float4*)(B + (size_t)(k0 + bk + 8) * Ncols + n0 + bn);
        __syncthreads();
#pragma unroll
        for (int kk = 0; kk < 16; kk++) {
            ull a0 = *(const ull*)&As2[kk][(ty * 4 + 0) * 2];
            ull a1 = *(const ull*)&As2[kk][(ty * 4 + 1) * 2];
            ull a2 = *(const ull*)&As2[kk][(ty * 4 + 2) * 2];
            ull a3 = *(const ull*)&As2[kk][(ty * 4 + 3) * 2];
            union { float4 f4; ull u[2]; } bu;
            bu.f4 = *(const float4*)&Bs[kk][tx * 4];
            FMA2(acc[0][0], a0, bu.u[0]); FMA2(acc[0][1], a0, bu.u[1]);
            FMA2(acc[1][0], a1, bu.u[0]); FMA2(acc[1][1], a1, bu.u[1]);
            FMA2(acc[2][0], a2, bu.u[0]); FMA2(acc[2][1], a2, bu.u[1]);
            FMA2(acc[3][0], a3, bu.u[0]); FMA2(acc[3][1], a3, bu.u[1]);
        }
        __syncthreads();
    }
#pragma unroll
    for (int i = 0; i < 4; i++) {
        int gm = m0 + ty * 4 + i;
        if (gm < M) {
            union { ull u[2]; float f[4]; } r;
            r.u[0] = acc[i][0]; r.u[1] = acc[i][1];
            *(float4*)(C + (size_t)gm * ldc + coff + n0 + tx * 4) =
                make_float4(r.f[0], r.f[1], r.f[2], r.f[3]);
        }
    }
}

// ---------------- vectorized scatter add ----------------
__global__ __launch_bounds__(256) void scatter_add_v4_kernel(
    const float4* __restrict__ m, const int* __restrict__ src,
    const int* __restrict__ dst, float* __restrict__ out, int nE, int lgF4)
{
    int idx = blockIdx.x * blockDim.x + threadIdx.x;
    int total = nE << lgF4;
    if (idx >= total) return;
    int e = idx >> lgF4;
    int f = idx & ((1 << lgF4) - 1);
    float4 v = m[((size_t)src[e] << lgF4) + f];
    red_add_v4(out + ((((size_t)dst[e] << lgF4) + f) << 2), v);
}

// ---------------- LayerNorm + bias + relu (row of 256) ----------------
__global__ __launch_bounds__(256) void ln_relu_kernel(
    const float* __restrict__ agg, const float* __restrict__ b1,
    const float* __restrict__ g1, const float* __restrict__ bt1, float* __restrict__ h1)
{
    int row = blockIdx.x;
    int tid = threadIdx.x;
    int lane = tid & 31, w = tid >> 5;
    float v = agg[(size_t)row * 256 + tid] + b1[tid];
    __shared__ float red[8];
    float s = v;
#pragma unroll
    for (int o = 16; o; o >>= 1) s += __shfl_xor_sync(0xffffffffu, s, o);
    if (lane == 0) red[w] = s;
    __syncthreads();
    float tot = 0.f;
#pragma unroll
    for (int i = 0; i < 8; i++) tot += red[i];
    float mu = tot * (1.f / 256.f);
    __syncthreads();
    float d = v - mu;
    float q = d * d;
#pragma unroll
    for (int o = 16; o; o >>= 1) q += __shfl_xor_sync(0xffffffffu, q, o);
    if (lane == 0) red[w] = q;
    __syncthreads();
    float tq = 0.f;
#pragma unroll
    for (int i = 0; i < 8; i++) tq += red[i];
    float var = tq * (1.f / 256.f);
    float o = d * rsqrtf(var + 1e-5f) * g1[tid] + bt1[tid];
    h1[(size_t)row * 256 + tid] = fmaxf(o, 0.f);
}

__device__ __forceinline__ void block_reduce_add_double(double v, double* gout)
{
    int lane = threadIdx.x & 31, w = threadIdx.x >> 5;
#pragma unroll
    for (int o = 16; o; o >>= 1) v += __shfl_xor_sync(0xffffffffu, v, o);
    __shared__ double s[8];
    if (lane == 0) s[w] = v;
    __syncthreads();
    if (threadIdx.x == 0) {
        double t = 0.0;
        int nw = (blockDim.x + 31) >> 5;
        for (int i = 0; i < nw; i++) t += s[i];
        atomicAdd(gout, t);
    }
}

// ---------------- z = mu + eps*exp(0.5*lv);  kl term accumulation ----------------
__global__ __launch_bounds__(256) void z_kl_kernel(
    const float* __restrict__ mulv, const float* __restrict__ eps,
    const float* __restrict__ bmu, const float* __restrict__ blv,
    float* __restrict__ z, double* __restrict__ acc)
{
    int idx = blockIdx.x * blockDim.x + threadIdx.x;
    float local = 0.f;
    if (idx < Nn * ZF) {
        int n = idx >> 6, j = idx & 63;
        float mu = mulv[(size_t)n * 128 + j] + bmu[j];
        float lv = mulv[(size_t)n * 128 + 64 + j] + blv[j];
        z[idx] = mu + eps[idx] * expf(0.5f * lv);
        local = 1.f + lv - mu * mu - expf(lv);
    }
    block_reduce_add_double((double)local, acc + 1);
}

__global__ void deg_kernel(const int* __restrict__ pd, int* __restrict__ deg)
{
    int e = blockIdx.x * blockDim.x + threadIdx.x;
    if (e < EP) atomicAdd(&deg[pd[e]], 1);
}

__global__ void dis_kernel(const int* __restrict__ deg, float* __restrict__ dis)
{
    int n = blockIdx.x * blockDim.x + threadIdx.x;
    if (n < Nn) dis[n] = rsqrtf((float)(deg[n] + 1));
}

// ---------------- normalized scatter for decoder GCN (v4) ----------------
__global__ __launch_bounds__(256) void scatter_norm_v4_kernel(
    const float4* __restrict__ m, const int* __restrict__ ps,
    const int* __restrict__ pd, const float* __restrict__ dis,
    float* __restrict__ out)
{
    int idx = blockIdx.x * blockDim.x + threadIdx.x;
    if (idx >= EP * 16) return;
    int e = idx >> 4, f = idx & 15;
    int s = ps[e], d = pd[e];
    float nrm = dis[s] * dis[d];
    float4 v = m[((size_t)s << 4) + f];
    v.x *= nrm; v.y *= nrm; v.z *= nrm; v.w *= nrm;
    red_add_v4(out + ((((size_t)d << 4) + f) << 2), v);
}

// ---------------- decoder finalize: self-loop + bias + relu ----------------
__global__ __launch_bounds__(256) void dec_fin_v4_kernel(
    const float4* aggv, const float4* __restrict__ m,
    const float* __restrict__ dis, const float4* __restrict__ bd, float4* outp)
{
    int idx = blockIdx.x * blockDim.x + threadIdx.x;
    if (idx >= Nn * 16) return;
    int n = idx >> 4, j = idx & 15;
    float di = dis[n];
    float sl = di * di;
    float4 a = aggv[idx], mm = m[idx], b = bd[j];
    float4 r;
    r.x = fmaxf(a.x + mm.x * sl + b.x, 0.f);
    r.y = fmaxf(a.y + mm.y * sl + b.y, 0.f);
    r.z = fmaxf(a.z + mm.z * sl + b.z, 0.f);
    r.w = fmaxf(a.w + mm.w * sl + b.w, 0.f);
    outp[idx] = r;
}

// ---------------- fused edge decoder + BCE loss (64-edge tiles) ----------------
__global__ __launch_bounds__(256) void edge_loss_kernel(
    const float* __restrict__ h, const float* __restrict__ A12,
    const float* __restrict__ Wa, const float* __restrict__ ba,
    const float* __restrict__ Wb, const float* __restrict__ bb,
    const float* __restrict__ tau,
    const int* __restrict__ pu, const int* __restrict__ pv,
    const int* __restrict__ nu, const int* __restrict__ nv,
    double* __restrict__ acc)
{
    extern __shared__ float sm[];
    float* sW = sm;                   // [128][64]  = 8192 floats
    float* sF = sW + 8192;            // [128][64]  = 8192 (k-major, edge-fast)
    float* sHU = sF + 8192;           // [64][65]   = 4160
    float* sHV = sHU + 4160;          // 4160
    int* sU = (int*)(sHV + 4160);     // 64
    int* sV = sU + 64;                // 64

    int tid = threadIdx.x;
    int lane = tid & 31, wid = tid >> 5;

    const float* W34 = Wa + 128 * 64;
    for (int i = tid; i < 8192; i += 256) sW[i] = W34[i];

    float tc = fmaxf(tau[0], 1e-4f);
    float invt = 1.0f / tc;
    float bbv = bb[0];
    float2 ba2 = ((const float2*)ba)[lane];
    float2 wb2 = ((const float2*)Wb)[lane];
    const float pw = (float)ENEG / (float)EP;
    double dsum = 0.0;

    int nTiles = ETOT / 64;  // 11250
    for (int tile = blockIdx.x; tile < nTiles; tile += gridDim.x) {
        __syncthreads();
        if (tid < 64) {
            int ge = tile * 64 + tid;
            int u, v;
            if (ge < EP) { u = pu[ge]; v = pv[ge]; }
            else         { u = nu[ge - EP]; v = nv[ge - EP]; }
            sU[tid] = u; sV[tid] = v;
        }
        __syncthreads();
#pragma unroll
        for (int ee = 0; ee < 8; ee++) {
            int e = wid * 8 + ee;
            int u = sU[e], v = sV[e];
            sHU[e * 65 + lane]      = h[(size_t)u * 64 + lane];
            sHU[e * 65 + 32 + lane] = h[(size_t)u * 64 + 32 + lane];
            sHV[e * 65 + lane]      = h[(size_t)v * 64 + lane];
            sHV[e * 65 + 32 + lane] = h[(size_t)v * 64 + 32 + lane];
        }
        __syncthreads();
#pragma unroll
        for (int p = 0; p < 16; p++) {
            int i = tid + p * 256;
            int e = i & 63, f = i >> 6;
            float hu = sHU[e * 65 + f], hv = sHV[e * 65 + f];
            sF[f * 64 + e]        = fabsf(hu - hv);
            sF[(64 + f) * 64 + e] = hu * hv;
        }
        __syncthreads();
        ull a[8];
#pragma unroll
        for (int i = 0; i < 8; i++) a[i] = 0ull;
        const float* fbase = sF + wid * 8;
#pragma unroll 4
        for (int k = 0; k < 128; k++) {
            float2 w = *(const float2*)&sW[k * 64 + 2 * lane];
            ull w0, w1;
            asm("mov.b64 %0, {%1, %1};" : "=l"(w0) : "f"(w.x));
            asm("mov.b64 %0, {%1, %1};" : "=l"(w1) : "f"(w.y));
            ulonglong2 fA = *(const ulonglong2*)(fbase + k * 64);
            ulonglong2 fB = *(const ulonglong2*)(fbase + k * 64 + 4);
            FMA2(a[0], fA.x, w0); FMA2(a[1], fA.y, w0);
            FMA2(a[2], fB.x, w0); FMA2(a[3], fB.y, w0);
            FMA2(a[4], fA.x, w1); FMA2(a[5], fA.y, w1);
            FMA2(a[6], fB.x, w1); FMA2(a[7], fB.y, w1);
        }
#pragma unroll
        for (int q = 0; q < 8; q++) {
            int e = wid * 8 + q;
            int u = sU[e], v = sV[e];
            union { ull uu; float f[2]; } c0, c1;
            c0.uu = a[q >> 1];
            c1.uu = a[4 + (q >> 1)];
            float v0 = c0.f[q & 1];
            float v1 = c1.f[q & 1];
            float2 au = *(const float2*)&A12[(size_t)u * 128 + 2 * lane];
            float2 av = *(const float2*)&A12[(size_t)v * 128 + 64 + 2 * lane];
            float t0 = v0 + au.x + av.x + ba2.x;
            float t1 = v1 + au.y + av.y + ba2.y;
            float r = fmaxf(t0, 0.f) * wb2.x + fmaxf(t1, 0.f) * wb2.y;
#pragma unroll
            for (int o = 16; o; o >>= 1) r += __shfl_xor_sync(0xffffffffu, r, o);
            if (lane == 0) {
                float l = (r + bbv) * invt;
                int ge = tile * 64 + e;
                float term;
                if (ge < EP) {
                    float ls = fminf(l, 0.f) - log1pf(expf(-fabsf(l)));
                    term = pw * ls;
                } else {
                    float ls = fminf(-l, 0.f) - log1pf(expf(-fabsf(l)));
                    term = ls;
                }
                dsum += (double)term;
            }
        }
    }
#pragma unroll
    for (int o = 16; o; o >>= 1) dsum += __shfl_xor_sync(0xffffffffu, dsum, o);
    __shared__ double sred[8];
    if (lane == 0) sred[wid] = dsum;
    __syncthreads();
    if (tid == 0) {
        double t = 0.0;
        for (int i = 0; i < 8; i++) t += sred[i];
        atomicAdd(acc, t);
    }
}

__global__ void finalize_kernel(const double* __restrict__ acc, float* __restrict__ out, int n)
{
    double recon = -acc[0] / (double)ETOT;
    double kl = -0.5 * acc[1] / ((double)Nn * 64.0);
    if (n >= 3) {
        out[0] = (float)(recon + kl);
        out[1] = (float)recon;
        out[2] = (float)kl;
    } else {
        out[0] = (float)(recon + kl);
    }
}

// ---------------- launch ----------------
extern "C" void kernel_launch(void* const* d_in, const int* in_sizes, int n_in,
                              void* d_out, int out_size)
{
    const float* x   = (const float*)d_in[0];
    const float* eps = (const float*)d_in[1];
    const int* edge_index = (const int*)d_in[2];
    const int* pos_edge   = (const int*)d_in[3];
    const int* neg_edge   = (const int*)d_in[4];
    const float* W1  = (const float*)d_in[5];
    const float* b1  = (const float*)d_in[6];
    const float* g1  = (const float*)d_in[7];
    const float* bt1 = (const float*)d_in[8];
    const float* Wmu = (const float*)d_in[9];
    const float* bmu = (const float*)d_in[10];
    const float* Wlv = (const float*)d_in[11];
    const float* blv = (const float*)d_in[12];
    const float* Wd1 = (const float*)d_in[13];
    const float* bd1 = (const float*)d_in[14];
    const float* Wd2 = (const float*)d_in[15];
    const float* bd2 = (const float*)d_in[16];
    const float* Wa  = (const float*)d_in[17];
    const float* ba  = (const float*)d_in[18];
    const float* Wb  = (const float*)d_in[19];
    const float* bb  = (const float*)d_in[20];
    const float* tau = (const float*)d_in[21];

    float *p_m, *p_agg, *p_h1, *p_tmulv, *p_mulv, *p_z, *p_md, *p_hd, *p_hd2, *p_A12, *p_Wcat, *p_dis;
    int* p_deg;
    double* p_acc;
    cudaGetSymbolAddress((void**)&p_m, g_m);
    cudaGetSymbolAddress((void**)&p_agg, g_agg);
    cudaGetSymbolAddress((void**)&p_h1, g_h1);
    cudaGetSymbolAddress((void**)&p_tmulv, g_tmulv);
    cudaGetSymbolAddress((void**)&p_mulv, g_mulv);
    cudaGetSymbolAddress((void**)&p_z, g_z);
    cudaGetSymbolAddress((void**)&p_md, g_md);
    cudaGetSymbolAddress((void**)&p_hd, g_hd);
    cudaGetSymbolAddress((void**)&p_hd2, g_hd2);
    cudaGetSymbolAddress((void**)&p_A12, g_A12);
    cudaGetSymbolAddress((void**)&p_Wcat, g_Wcat);
    cudaGetSymbolAddress((void**)&p_dis, g_dis);
    cudaGetSymbolAddress((void**)&p_deg, g_deg);
    cudaGetSymbolAddress((void**)&p_acc, g_acc);

    const int* src = edge_index;
    const int* dst = edge_index + E2;
    const int* pu = pos_edge;
    const int* pv = pos_edge + EP;
    const int* nu = neg_edge;
    const int* nv = neg_edge + ENEG;

    // ---- one fused zero of all scatter targets + accumulators ----
    {
        int na = Nn * HIDF / 4;   // agg
        int nb = Nn * 128 / 4;    // mulv
        int nc = Nn * 64 / 4;     // hd
        int nd = Nn * 64 / 4;     // hd2
        int ne = Nn / 4;          // deg (ints as float4)
        long total = (long)na + nb + nc + nd + ne;
        zero_kernel<<<(int)((total + 255) / 256), 256>>>(
            (float4*)p_agg, na, (float4*)p_mulv, nb, (float4*)p_hd, nc,
            (float4*)p_hd2, nd, (float4*)p_deg, ne, p_acc);
    }

    // ---- encoder layer 1 ----
    {
        dim3 g(4, (Nn + 63) / 64);
        sgemm_kernel<<<g, 256>>>(x, W1, p_m, Nn, 256, 256, 256, 0);
    }
    {
        int total = E2 * 64;
        scatter_add_v4_kernel<<<(total + 255) / 256, 256>>>(
            (const float4*)p_m, src, dst, p_agg, E2, 6);
    }
    ln_relu_kernel<<<Nn, 256>>>(p_agg, b1, g1, bt1, p_h1);

    // ---- decoder degree (independent; early for overlap slack) ----
    deg_kernel<<<(EP + 255) / 256, 256>>>(pv, p_deg);
    dis_kernel<<<(Nn + 255) / 256, 256>>>(p_deg, p_dis);

    // ---- mu / logvar: fused N=128 gemm on packed [Wmu|Wlv] ----
    pack2_kernel<<<(256 * 64 + 255) / 256, 256>>>(Wmu, Wlv, p_Wcat, 256);
    {
        dim3 g(2, (Nn + 31) / 32);
        sgemm32_kernel<<<g, 128>>>(p_h1, p_Wcat, p_tmulv, Nn, 128, 256, 128, 0);
    }
    {
        int total = E2 * 32;
        scatter_add_v4_kernel<<<(total + 255) / 256, 256>>>(
            (const float4*)p_tmulv, src, dst, p_mulv, E2, 5);
    }
    z_kl_kernel<<<(Nn * 64 + 255) / 256, 256>>>(p_mulv, eps, bmu, blv, p_z, p_acc);

    // ---- decoder GCN pass 1 ----
    {
        dim3 g(1, (Nn + 31) / 32);
        sgemm32_kernel<<<g, 128>>>(p_z, Wd1, p_md, Nn, 64, 64, 64, 0);
    }
    scatter_norm_v4_kernel<<<(EP * 16 + 255) / 256, 256>>>(
        (const float4*)p_md, pu, pv, p_dis, p_hd);
    dec_fin_v4_kernel<<<(Nn * 16 + 255) / 256, 256>>>(
        (const float4*)p_hd, (const float4*)p_md, p_dis, (const float4*)bd1, (float4*)p_hd);

    // ---- decoder GCN pass 2 ----
    {
        dim3 g(1, (Nn + 31) / 32);
        sgemm32_kernel<<<g, 128>>>(p_hd, Wd2, p_md, Nn, 64, 64, 64, 0);
    }
    // hd2 was zeroed at start; safe because nothing wrote it yet
    scatter_norm_v4_kernel<<<(EP * 16 + 255) / 256, 256>>>(
        (const float4*)p_md, pu, pv, p_dis, p_hd2);
    dec_fin_v4_kernel<<<(Nn * 16 + 255) / 256, 256>>>(
        (const float4*)p_hd2, (const float4*)p_md, p_dis, (const float4*)bd2, (float4*)p_hd2);

    // ---- per-node precompute [h@Wa1 | h@Wa2]: fused N=128 gemm ----
    pack2_kernel<<<(64 * 64 + 255) / 256, 256>>>(Wa, Wa + 64 * 64, p_Wcat, 64);
    {
        dim3 g(2, (Nn + 31) / 32);
        sgemm32_kernel<<<g, 128>>>(p_hd2, p_Wcat, p_A12, Nn, 128, 64, 128, 0);
    }

    // ---- fused edge decoder + loss ----
    {
        int smem = (8192 + 8192 + 4160 + 4160) * 4 + 128 * 4;   // 99328 B
        cudaFuncSetAttribute(edge_loss_kernel, cudaFuncAttributeMaxDynamicSharedMemorySize, smem);
        edge_loss_kernel<<<296, 256, smem>>>(p_hd2, p_A12, Wa, ba, Wb, bb, tau,
                                             pu, pv, nu, nv, p_acc);
    }

    finalize_kernel<<<1, 1>>>(p_acc, (float*)d_out, out_size);

    (void)in_sizes; (void)n_in;
}